// round 3
// baseline (speedup 1.0000x reference)
#include <cuda_runtime.h>
#include <cstdint>

// Scene constants
#define DIM_X 256
#define DIM_Y 256
#define DIM_Z 32
#define DIM_T 5
#define NVOX  (DIM_T * DIM_Z * DIM_Y * DIM_X)   // 10,485,760
#define MASK_WORDS (NVOX / 32)                   // 327,680
#define NK 81
#define CIN 8
#define COUT 8

// Scratch (allocation-free rule: __device__ globals)
__device__ unsigned int g_mask[MASK_WORDS];
__device__ float g_wsum[NK * COUT];

// Quantization matching XLA-CPU fast-math: division by constant 0.2f is
// folded to multiply by its reciprocal, and rcp(0.2f) rounds to EXACTLY 5.0f.
// So the reference computes floor((p - bmin) * 5.0f). Use explicit _rn
// intrinsics so nvcc cannot contract or re-lower this.
__device__ __forceinline__ int quant(float p, float negbmin) {
    return (int)floorf(__fmul_rn(__fadd_rn(p, negbmin), 5.0f));
}

__device__ __forceinline__ int4 point_coords(float4 p) {
    int x = quant(p.x, 25.6f);
    int y = quant(p.y, 25.6f);
    int z = quant(p.z, 3.2f);
    int t = (int)floorf(p.w);           // scale 1, offset 0 -> exact
    x = min(max(x, 0), DIM_X - 1);
    y = min(max(y, 0), DIM_Y - 1);
    z = min(max(z, 0), DIM_Z - 1);
    t = min(max(t, 0), DIM_T - 1);
    return make_int4(x, y, z, t);
}

__device__ __forceinline__ int flat_id(int x, int y, int z, int t) {
    return ((t * DIM_Z + z) * DIM_Y + y) * DIM_X + x;
}

// Kernel 1: zero occupancy mask; first 648 threads also compute
// Wsum[k][f] = sum_c W[k][c][f]
__global__ void k_zero_mask_wsum(const float* __restrict__ W) {
    int i = blockIdx.x * blockDim.x + threadIdx.x;
    if (i < MASK_WORDS) g_mask[i] = 0u;
    if (i < NK * COUT) {
        int k = i >> 3;       // /COUT
        int f = i & 7;        // %COUT
        float s = 0.0f;
        #pragma unroll
        for (int c = 0; c < CIN; c++)
            s += W[(k * CIN + c) * COUT + f];
        g_wsum[i] = s;
    }
}

// Kernel 2: set occupancy bits from points
__global__ void k_build_mask(const float4* __restrict__ pts, int n) {
    int i = blockIdx.x * blockDim.x + threadIdx.x;
    if (i >= n) return;
    int4 c = point_coords(pts[i]);
    int vid = flat_id(c.x, c.y, c.z, c.w);
    atomicOr(&g_mask[vid >> 5], 1u << (vid & 31));
}

// Per-active-voxel 81-neighbor Wsum reduction (rare path, ~1% of voxels)
__device__ __noinline__ void compute_voxel(int v, const float* __restrict__ swsum,
                                           float* __restrict__ res /*[8]*/) {
    int x = v & 0xFF;
    int y = (v >> 8) & 0xFF;
    int z = (v >> 16) & 31;
    int t = v >> 21;

    float a0 = 0.f, a1 = 0.f, a2 = 0.f, a3 = 0.f;
    float a4 = 0.f, a5 = 0.f, a6 = 0.f, a7 = 0.f;

    // OFFSETS order: meshgrid over (x,y,z,t) 'ij' -> x slowest, t fastest
    int k = 0;
    for (int dx = -1; dx <= 1; dx++) {
        int nx = x + dx;
        bool bx = (unsigned)nx < (unsigned)DIM_X;
        for (int dy = -1; dy <= 1; dy++) {
            int ny = y + dy;
            bool bxy = bx && ((unsigned)ny < (unsigned)DIM_Y);
            for (int dz = -1; dz <= 1; dz++) {
                int nz = z + dz;
                bool bxyz = bxy && ((unsigned)nz < (unsigned)DIM_Z);
                for (int dt = -1; dt <= 1; dt++, k++) {
                    int nt = t + dt;
                    if (bxyz && ((unsigned)nt < (unsigned)DIM_T)) {
                        int nid = flat_id(nx, ny, nz, nt);
                        unsigned w = __ldg(&g_mask[nid >> 5]);
                        if ((w >> (nid & 31)) & 1u) {
                            const float* ws = &swsum[k * COUT];
                            a0 += ws[0]; a1 += ws[1]; a2 += ws[2]; a3 += ws[3];
                            a4 += ws[4]; a5 += ws[5]; a6 += ws[6]; a7 += ws[7];
                        }
                    }
                }
            }
        }
    }
    res[0] = fmaxf(a0, 0.f); res[1] = fmaxf(a1, 0.f);
    res[2] = fmaxf(a2, 0.f); res[3] = fmaxf(a3, 0.f);
    res[4] = fmaxf(a4, 0.f); res[5] = fmaxf(a5, 0.f);
    res[6] = fmaxf(a6, 0.f); res[7] = fmaxf(a7, 0.f);
}

// Kernel 3: fused zero-fill + gather. Each thread owns 4 x-consecutive voxels.
// Inactive (nibble==0, ~99%): stream zeros, 8 coalesced float4 stores.
// Active: compute the voxel's output from the 81-neighbor mask reduction.
// Output written exactly once -> single 335 MB store pass.
__global__ void k_write(float* __restrict__ out) {
    __shared__ float swsum[NK * COUT];
    for (int i = threadIdx.x; i < NK * COUT; i += blockDim.x)
        swsum[i] = g_wsum[i];
    __syncthreads();

    int tid = blockIdx.x * blockDim.x + threadIdx.x;
    int v0 = tid * 4;                       // 4 voxels per thread
    if (v0 >= NVOX) return;

    unsigned word = __ldg(&g_mask[v0 >> 5]);
    unsigned nib = (word >> (v0 & 31)) & 0xFu;

    if (nib == 0u) {
        float4 z4 = make_float4(0.f, 0.f, 0.f, 0.f);
        #pragma unroll
        for (int f = 0; f < COUT; f++)
            *reinterpret_cast<float4*>(out + (size_t)f * NVOX + v0) = z4;
        return;
    }

    float res[4][COUT];
    #pragma unroll
    for (int j = 0; j < 4; j++)
        #pragma unroll
        for (int f = 0; f < COUT; f++)
            res[j][f] = 0.f;

    for (int j = 0; j < 4; j++)
        if ((nib >> j) & 1u)
            compute_voxel(v0 + j, swsum, res[j]);

    #pragma unroll
    for (int f = 0; f < COUT; f++) {
        float4 v4 = make_float4(res[0][f], res[1][f], res[2][f], res[3][f]);
        *reinterpret_cast<float4*>(out + (size_t)f * NVOX + v0) = v4;
    }
}

extern "C" void kernel_launch(void* const* d_in, const int* in_sizes, int n_in,
                              void* d_out, int out_size) {
    const float* pts = (const float*)d_in[0];   // [1, N, 4] float32
    const float* W   = (const float*)d_in[1];   // [81, 8, 8] float32
    float* out = (float*)d_out;                 // [1, 8, 5, 32, 256, 256] float32

    int n = in_sizes[0] / 4;

    // 1) zero occupancy mask + compute Wsum
    {
        int threads = 256;
        int blocks = (MASK_WORDS + threads - 1) / threads;
        k_zero_mask_wsum<<<blocks, threads>>>(W);
    }

    // 2) build occupancy mask from points
    {
        int threads = 256;
        int blocks = (n + threads - 1) / threads;
        k_build_mask<<<blocks, threads>>>((const float4*)pts, n);
    }

    // 3) fused zero-fill + gather-write of the whole dense output
    {
        int threads = 256;
        int vox_per_block = threads * 4;
        int blocks = (NVOX + vox_per_block - 1) / vox_per_block;  // 10240
        k_write<<<blocks, threads>>>(out);
    }
}

// round 4
// speedup vs baseline: 2.1679x; 2.1679x over previous
#include <cuda_runtime.h>
#include <cstdint>

// Scene constants
#define DIM_X 256
#define DIM_Y 256
#define DIM_Z 32
#define DIM_T 5
#define NVOX  (DIM_T * DIM_Z * DIM_Y * DIM_X)   // 10,485,760
#define MASK_WORDS (NVOX / 32)                   // 327,680
#define NK 81
#define CIN 8
#define COUT 8

// Scratch (allocation-free rule: __device__ globals)
__device__ unsigned int g_mask[MASK_WORDS];
__device__ float g_wsum[NK * COUT];

// Quantization matching XLA fast-math: division by constant 0.2f is folded to
// multiply by its reciprocal, and rcp(0.2f) rounds to EXACTLY 5.0f. So the
// reference computes floor((p - bmin) * 5.0f). Explicit _rn intrinsics keep
// nvcc from contracting/re-lowering this. (Verified bit-exact in R3:
// rel_err 9e-8.)
__device__ __forceinline__ int quant(float p, float negbmin) {
    return (int)floorf(__fmul_rn(__fadd_rn(p, negbmin), 5.0f));
}

__device__ __forceinline__ int4 point_coords(float4 p) {
    int x = quant(p.x, 25.6f);
    int y = quant(p.y, 25.6f);
    int z = quant(p.z, 3.2f);
    int t = (int)floorf(p.w);           // scale 1, offset 0 -> exact
    x = min(max(x, 0), DIM_X - 1);
    y = min(max(y, 0), DIM_Y - 1);
    z = min(max(z, 0), DIM_Z - 1);
    t = min(max(t, 0), DIM_T - 1);
    return make_int4(x, y, z, t);
}

__device__ __forceinline__ int flat_id(int x, int y, int z, int t) {
    return ((t * DIM_Z + z) * DIM_Y + y) * DIM_X + x;
}

// Kernel 1: zero occupancy mask; first 648 threads also compute
// Wsum[k][f] = sum_c W[k][c][f]
__global__ void k_zero_mask_wsum(const float* __restrict__ W) {
    int i = blockIdx.x * blockDim.x + threadIdx.x;
    if (i < MASK_WORDS) g_mask[i] = 0u;
    if (i < NK * COUT) {
        int k = i >> 3;       // /COUT
        int f = i & 7;        // %COUT
        float s = 0.0f;
        #pragma unroll
        for (int c = 0; c < CIN; c++)
            s += W[(k * CIN + c) * COUT + f];
        g_wsum[i] = s;
    }
}

// Kernel 2: set occupancy bits from points
__global__ void k_build_mask(const float4* __restrict__ pts, int n) {
    int i = blockIdx.x * blockDim.x + threadIdx.x;
    if (i >= n) return;
    int4 c = point_coords(pts[i]);
    int vid = flat_id(c.x, c.y, c.z, c.w);
    atomicOr(&g_mask[vid >> 5], 1u << (vid & 31));
}

// Kernel 3: per point, 81-neighbor occupancy reduction -> relu -> 8 scattered
// stores. Runs AFTER the output memset; only touches active voxels.
// Duplicate points in a voxel write identical values to identical addresses
// (benign). Loop structured as 27 x (dy,dz,dt) with the 3 x-neighbors peeled:
// they share (or neighbor) one mask word, so ~27 effective L1/L2-resident
// loads per point.
__global__ void k_scatter(const float4* __restrict__ pts, int n,
                          float* __restrict__ out) {
    __shared__ float swsum[NK * COUT];
    for (int i = threadIdx.x; i < NK * COUT; i += blockDim.x)
        swsum[i] = g_wsum[i];
    __syncthreads();

    int i = blockIdx.x * blockDim.x + threadIdx.x;
    if (i >= n) return;

    int4 c = point_coords(pts[i]);
    int vid = flat_id(c.x, c.y, c.z, c.w);

    float a0 = 0.f, a1 = 0.f, a2 = 0.f, a3 = 0.f;
    float a4 = 0.f, a5 = 0.f, a6 = 0.f, a7 = 0.f;

    // k = (dx+1)*27 + (dy+1)*9 + (dz+1)*3 + (dt+1)  [meshgrid 'ij' order]
    #pragma unroll
    for (int dy = -1; dy <= 1; dy++) {
        int ny = c.y + dy;
        if ((unsigned)ny >= (unsigned)DIM_Y) continue;
        #pragma unroll
        for (int dz = -1; dz <= 1; dz++) {
            int nz = c.z + dz;
            if ((unsigned)nz >= (unsigned)DIM_Z) continue;
            #pragma unroll
            for (int dt = -1; dt <= 1; dt++) {
                int nt = c.w + dt;
                if ((unsigned)nt >= (unsigned)DIM_T) continue;
                int nbase = flat_id(c.x, ny, nz, nt);
                int kbase = (dy + 1) * 9 + (dz + 1) * 3 + (dt + 1);
                #pragma unroll
                for (int dxi = 0; dxi < 3; dxi++) {
                    int nx = c.x + dxi - 1;
                    if ((unsigned)nx < (unsigned)DIM_X) {
                        int nid = nbase + dxi - 1;
                        unsigned w = __ldg(&g_mask[nid >> 5]);
                        if ((w >> (nid & 31)) & 1u) {
                            const float* ws = &swsum[(dxi * 27 + kbase) * COUT];
                            a0 += ws[0]; a1 += ws[1]; a2 += ws[2]; a3 += ws[3];
                            a4 += ws[4]; a5 += ws[5]; a6 += ws[6]; a7 += ws[7];
                        }
                    }
                }
            }
        }
    }

    // output layout: [COUT, T, Z, Y, X] -> out[f * NVOX + vid]
    size_t v = (size_t)vid;
    out[0 * (size_t)NVOX + v] = fmaxf(a0, 0.f);
    out[1 * (size_t)NVOX + v] = fmaxf(a1, 0.f);
    out[2 * (size_t)NVOX + v] = fmaxf(a2, 0.f);
    out[3 * (size_t)NVOX + v] = fmaxf(a3, 0.f);
    out[4 * (size_t)NVOX + v] = fmaxf(a4, 0.f);
    out[5 * (size_t)NVOX + v] = fmaxf(a5, 0.f);
    out[6 * (size_t)NVOX + v] = fmaxf(a6, 0.f);
    out[7 * (size_t)NVOX + v] = fmaxf(a7, 0.f);
}

extern "C" void kernel_launch(void* const* d_in, const int* in_sizes, int n_in,
                              void* d_out, int out_size) {
    const float* pts = (const float*)d_in[0];   // [1, N, 4] float32
    const float* W   = (const float*)d_in[1];   // [81, 8, 8] float32
    float* out = (float*)d_out;                 // [1, 8, 5, 32, 256, 256] float32

    int n = in_sizes[0] / 4;

    // 1) zero the dense output with the driver's peak-BW memset (~335 MB)
    cudaMemsetAsync(d_out, 0, (size_t)out_size * sizeof(float));

    // 2) zero occupancy mask + compute Wsum
    {
        int threads = 256;
        int blocks = (MASK_WORDS + threads - 1) / threads;
        k_zero_mask_wsum<<<blocks, threads>>>(W);
    }

    // 3) build occupancy mask from points
    {
        int threads = 256;
        int blocks = (n + threads - 1) / threads;
        k_build_mask<<<blocks, threads>>>((const float4*)pts, n);
    }

    // 4) per-point neighbor aggregation + scatter of active voxels only
    {
        int threads = 128;
        int blocks = (n + threads - 1) / threads;
        k_scatter<<<blocks, threads>>>((const float4*)pts, n, out);
    }
}